// round 14
// baseline (speedup 1.0000x reference)
#include <cuda_runtime.h>
#include <cuda_bf16.h>
#include <cstddef>
#include <cstdint>

#define NND 100000
#define NPAD 100096                  // padded to multiple of 128
#define EE  1600000
#define RR  8
#define BB  4
#define DD  64
#define NCH ((NND + 1023) / 1024)    // 98 scan chunks
#define NT2 (NPAD / 128)             // 782 p2 tiles

typedef unsigned long long ull;
typedef unsigned int uint;

// Scratch (no runtime allocation allowed) ------------------------------------
__device__ float g_h1[(size_t)NND * DD];
__device__ float g_h2[(size_t)NND * DD];
__device__ uint  g_Ahi[(size_t)NPAD * 128];   // aggB hi bf16 pairs (51.2 MB)
__device__ uint  g_Alo[(size_t)NPAD * 128];   // aggB lo bf16 pairs
__device__ uint  g_Bth[3][64 * 128];          // B^T hi bf16 pairs per layer
__device__ uint  g_Btl[3][64 * 128];          // B^T lo
__device__ int   g_deg[NND];
__device__ int   g_rowptr[NND + 1];
__device__ int   g_cur[NND];
__device__ ull   g_partial[NCH];
__device__ ull   g_edata[EE];                 // (norm<<32)|(ety<<20)|src

// ---------------------------------------------------------------- f32x2 utils
__device__ __forceinline__ void fma2(ull& a, ull x, ull b) {
    asm("fma.rn.f32x2 %0, %1, %2, %0;" : "+l"(a) : "l"(x), "l"(b));
}
__device__ __forceinline__ ull mul2(ull x, ull y) {
    ull r; asm("mul.rn.f32x2 %0, %1, %2;" : "=l"(r) : "l"(x), "l"(y)); return r;
}
__device__ __forceinline__ ull dup2(float x) {
    ull r; asm("mov.b64 %0, {%1, %1};" : "=l"(r) : "f"(x)); return r;
}
__device__ __forceinline__ float2 unp2(ull v) {
    float2 r; asm("mov.b64 {%0, %1}, %2;" : "=f"(r.x), "=f"(r.y) : "l"(v));
    return r;
}

// pack (x -> low 16, y -> high 16) as bf16x2
#define CVTBF2(r, x, y) \
    asm("cvt.rn.bf16x2.f32 %0, %1, %2;" : "=r"(r) : "f"(y), "f"(x))

// split a packed fp32 pair into bf16 hi + bf16 lo(residual)
__device__ __forceinline__ void bf16split(ull a, uint& h, uint& l) {
    const float2 v = unp2(a);
    CVTBF2(h, v.x, v.y);
    const float fx = __uint_as_float(h << 16);
    const float fy = __uint_as_float(h & 0xFFFF0000u);
    CVTBF2(l, v.x - fx, v.y - fy);
}

// legacy HMMA: m16n8k16 bf16*bf16 + f32 (baseline PTX, no 'a' features)
#define MMA(c, a0, a1, a2, a3, b0, b1) \
    asm volatile("mma.sync.aligned.m16n8k16.row.col.f32.bf16.bf16.f32 " \
        "{%0,%1,%2,%3}, {%4,%5,%6,%7}, {%8,%9}, {%0,%1,%2,%3};" \
        : "+f"((c)[0]), "+f"((c)[1]), "+f"((c)[2]), "+f"((c)[3]) \
        : "r"(a0), "r"(a1), "r"(a2), "r"(a3), "r"(b0), "r"(b1))

// ----------------------------------------------------------------- CSR build
__global__ void __launch_bounds__(256) hist_kernel(const int* __restrict__ dst) {
    for (long long e = (long long)blockIdx.x * 256 + threadIdx.x; e < EE;
         e += (long long)gridDim.x * 256)
        atomicAdd(&g_deg[dst[e]], 1);
}

__global__ void __launch_bounds__(256) scan_kernel() {
    __shared__ int s[256];
    __shared__ int pre;
    const int b = blockIdx.x, t = threadIdx.x;

    int v[4];
    #pragma unroll
    for (int j = 0; j < 4; j++) {
        int i = b * 1024 + t * 4 + j;
        v[j] = (i < NND) ? g_deg[i] : 0;
    }
    const int tot = v[0] + v[1] + v[2] + v[3];
    s[t] = tot; __syncthreads();
    for (int off = 1; off < 256; off <<= 1) {
        int x = (t >= off) ? s[t - off] : 0;
        __syncthreads();
        s[t] += x;
        __syncthreads();
    }
    if (t == 255)
        atomicExch(&g_partial[b], (1ull << 32) | (uint)s[255]);

    __shared__ int predsum[128];
    if (t < 128) predsum[t] = 0;
    __syncthreads();
    if (t < b) {
        ull p;
        do { p = atomicAdd(&g_partial[t], 0ull); } while (!(p >> 32));
        predsum[t] = (int)(uint)p;
    }
    __syncthreads();
    if (t == 0) {
        int acc = 0;
        for (int i = 0; i < b; i++) acc += predsum[i];
        pre = acc;
    }
    __syncthreads();

    int run = pre + s[t] - tot;
    #pragma unroll
    for (int j = 0; j < 4; j++) {
        int i = b * 1024 + t * 4 + j;
        if (i < NND) { g_rowptr[i] = run; g_cur[i] = run; }
        run += v[j];
    }
    if (b == 0 && t == 0) g_rowptr[NND] = EE;
}

__global__ void __launch_bounds__(256) csr_scatter_kernel(
    const int* __restrict__ src, const int* __restrict__ dst,
    const int* __restrict__ ety, const float* __restrict__ norm)
{
    for (long long e = (long long)blockIdx.x * 256 + threadIdx.x; e < EE;
         e += (long long)gridDim.x * 256) {
        const int d = dst[e];
        const int pos = atomicAdd(&g_cur[d], 1);
        const ull v = ((ull)__float_as_uint(norm[e]) << 32)
                    | (uint)(src[e] | (ety[e] << 20));
        g_edata[pos] = v;
    }
}

// ----------------------------------------------------------------------------
// B prep: B^T[o][k] = bases[k>>6][k&63][o], split bf16 hi/lo, store k-pairs.
// One thread per (layer, o, k-pair): 3 * 64 * 128 = 24576 threads.
// ----------------------------------------------------------------------------
__global__ void __launch_bounds__(256) bprep_kernel(
    const float* __restrict__ b0, const float* __restrict__ b1,
    const float* __restrict__ b2)
{
    const int idx = blockIdx.x * 256 + threadIdx.x;
    if (idx >= 3 * 64 * 128) return;
    const int layer = idx / (64 * 128);
    const int rem = idx % (64 * 128);
    const int o = rem >> 7;           // 0..63
    const int kp = rem & 127;         // k-pair, k = 2*kp
    const int k = 2 * kp;
    const int b = k >> 6, i = k & 63;
    const float* bp = (layer == 0) ? b0 : (layer == 1) ? b1 : b2;
    const float v0 = bp[b * DD * DD + i * DD + o];
    const float v1 = bp[b * DD * DD + (i + 1) * DD + o];

    uint h; CVTBF2(h, v0, v1);
    const float f0 = __uint_as_float(h << 16);
    const float f1 = __uint_as_float(h & 0xFFFF0000u);
    uint l; CVTBF2(l, v0 - f0, v1 - f1);
    g_Bth[layer][o * 128 + kp] = h;
    g_Btl[layer][o * 128 + kp] = l;
}

// ----------------------------------------------------------------------------
// Phase 1: aggB[row][b*64+2*lane..] = sum_{e->row} wcomp[ety,b]*norm * X[src]
// warp per row, 6 edges in flight; stores bf16 hi/lo packed (uint per pair).
// ----------------------------------------------------------------------------
__global__ void __launch_bounds__(256) p1_kernel(
    const float* __restrict__ Xin, const float* __restrict__ wcomp,
    const int* __restrict__ rowptr, const ull* __restrict__ edata,
    uint* __restrict__ Ahi, uint* __restrict__ Alo)
{
    __shared__ ull wc2[RR * BB];
    const int tid = threadIdx.x;
    if (tid < RR * BB) wc2[tid] = dup2(wcomp[tid]);
    __syncthreads();

    const int lane = tid & 31;
    const int gw = blockIdx.x * 8 + (tid >> 5);
    const int W = gridDim.x * 8;

    for (int row = gw; row < NND; row += W) {
        const int beg = rowptr[row];
        const int end = rowptr[row + 1];

        ull a0 = 0, a1 = 0, a2 = 0, a3 = 0;
        for (int e = beg; e < end; e += 6) {
            ull ed[6];
            #pragma unroll
            for (int j = 0; j < 6; j++) {
                const int idx = (e + j < end) ? e + j : end - 1;
                ed[j] = __ldg(edata + idx);
            }
            ull xv[6];
            #pragma unroll
            for (int j = 0; j < 6; j++) {
                const int s = (uint)ed[j] & 0xFFFFF;
                xv[j] = *(const ull*)(Xin + (size_t)s * DD + 2 * lane);
            }
            #pragma unroll
            for (int j = 0; j < 6; j++) {
                float nm = __uint_as_float((uint)(ed[j] >> 32));
                if (e + j >= end) nm = 0.f;
                const int r = ((uint)ed[j] >> 20) & 7;
                const ull xnm = mul2(xv[j], dup2(nm));
                const ulonglong2 wA = *(const ulonglong2*)&wc2[r * 4 + 0];
                const ulonglong2 wB = *(const ulonglong2*)&wc2[r * 4 + 2];
                fma2(a0, wA.x, xnm);
                fma2(a1, wA.y, xnm);
                fma2(a2, wB.x, xnm);
                fma2(a3, wB.y, xnm);
            }
        }
        uint h, l;
        uint* ph = Ahi + (size_t)row * 128 + lane;
        uint* pl = Alo + (size_t)row * 128 + lane;
        bf16split(a0, h, l); ph[0]  = h; pl[0]  = l;
        bf16split(a1, h, l); ph[32] = h; pl[32] = l;
        bf16split(a2, h, l); ph[64] = h; pl[64] = l;
        bf16split(a3, h, l); ph[96] = h; pl[96] = l;
    }
}

// ----------------------------------------------------------------------------
// Phase 2 (HMMA): Out[128-tile][64] = aggB @ B^T via 3-term bf16 split.
// 8 warps x (M16 x N64) per block; fragments loaded straight from global
// (A streams through L2, B is L1-resident). fp32 accum; fused ReLU on store.
// ----------------------------------------------------------------------------
__global__ void __launch_bounds__(256) p2_kernel(
    const uint* __restrict__ Ahi, const uint* __restrict__ Alo,
    const uint* __restrict__ Bhi, const uint* __restrict__ Blo,
    float* __restrict__ Out, int relu_out)
{
    const int tid = threadIdx.x;
    const int warp = tid >> 5, lane = tid & 31;
    const int g = lane >> 2, tig = lane & 3;
    const int m0 = blockIdx.x * 128 + warp * 16;

    float acc[8][4];
    #pragma unroll
    for (int n = 0; n < 8; n++) {
        acc[n][0] = 0.f; acc[n][1] = 0.f; acc[n][2] = 0.f; acc[n][3] = 0.f;
    }

    const uint* ar0h = Ahi + (size_t)(m0 + g) * 128 + tig;
    const uint* ar1h = Ahi + (size_t)(m0 + g + 8) * 128 + tig;
    const uint* ar0l = Alo + (size_t)(m0 + g) * 128 + tig;
    const uint* ar1l = Alo + (size_t)(m0 + g + 8) * 128 + tig;
    const uint* bb = Bhi + g * 128 + tig;
    const uint* bl = Blo + g * 128 + tig;

    #pragma unroll 4
    for (int k0 = 0; k0 < 256; k0 += 16) {
        const int ku = k0 >> 1;
        const uint ah0 = __ldg(ar0h + ku),     ah2 = __ldg(ar0h + ku + 4);
        const uint ah1 = __ldg(ar1h + ku),     ah3 = __ldg(ar1h + ku + 4);
        const uint al0 = __ldg(ar0l + ku),     al2 = __ldg(ar0l + ku + 4);
        const uint al1 = __ldg(ar1l + ku),     al3 = __ldg(ar1l + ku + 4);
        #pragma unroll
        for (int nt = 0; nt < 8; nt++) {
            const uint bh0 = __ldg(bb + nt * 1024 + ku);
            const uint bh1 = __ldg(bb + nt * 1024 + ku + 4);
            const uint bl0 = __ldg(bl + nt * 1024 + ku);
            const uint bl1 = __ldg(bl + nt * 1024 + ku + 4);
            MMA(acc[nt], ah0, ah1, ah2, ah3, bh0, bh1);
            MMA(acc[nt], ah0, ah1, ah2, ah3, bl0, bl1);
            MMA(acc[nt], al0, al1, al2, al3, bh0, bh1);
        }
    }

    const int r0 = m0 + g, r1 = m0 + g + 8;
    #pragma unroll
    for (int nt = 0; nt < 8; nt++) {
        float2 v0 = make_float2(acc[nt][0], acc[nt][1]);
        float2 v1 = make_float2(acc[nt][2], acc[nt][3]);
        if (relu_out) {
            v0.x = fmaxf(v0.x, 0.f); v0.y = fmaxf(v0.y, 0.f);
            v1.x = fmaxf(v1.x, 0.f); v1.y = fmaxf(v1.y, 0.f);
        }
        const int c = nt * 8 + 2 * tig;
        if (r0 < NND) *(float2*)(Out + (size_t)r0 * DD + c) = v0;
        if (r1 < NND) *(float2*)(Out + (size_t)r1 * DD + c) = v1;
    }
}

// ----------------------------------------------------------------------------
// Decoder: rec[n] = (relu(henc[n] @ W1 + b1)) @ W2 + b2.  One warp per node.
// ----------------------------------------------------------------------------
__global__ void __launch_bounds__(256) decoder_kernel(
    const float* __restrict__ henc, const float* __restrict__ w1,
    const float* __restrict__ b1, const float* __restrict__ w2,
    const float* __restrict__ b2, float* __restrict__ rec)
{
    __shared__ float w1s[DD * DD];
    __shared__ float w2s[DD], b1s[DD];
    __shared__ float b2s;
    const int tid = threadIdx.x;
    for (int i = tid; i < DD * DD; i += 256) w1s[i] = w1[i];
    if (tid < DD) { w2s[tid] = w2[tid]; b1s[tid] = b1[tid]; }
    if (tid == 0) b2s = b2[0];
    __syncthreads();

    const int lane = tid & 31;
    const int w = tid >> 5;
    for (int node = blockIdx.x * 8 + w; node < NND; node += gridDim.x * 8) {
        const float xa = henc[(size_t)node * DD + lane];
        const float xb = henc[(size_t)node * DD + 32 + lane];
        float s0 = b1s[lane], s1 = b1s[lane + 32];
        #pragma unroll
        for (int i = 0; i < 32; i++) {
            const float xi = __shfl_sync(0xffffffffu, xa, i);
            s0 += xi * w1s[i * DD + lane];
            s1 += xi * w1s[i * DD + lane + 32];
        }
        #pragma unroll
        for (int i = 0; i < 32; i++) {
            const float xi = __shfl_sync(0xffffffffu, xb, i);
            s0 += xi * w1s[(32 + i) * DD + lane];
            s1 += xi * w1s[(32 + i) * DD + lane + 32];
        }
        s0 = fmaxf(s0, 0.f); s1 = fmaxf(s1, 0.f);
        float v = s0 * w2s[lane] + s1 * w2s[lane + 32];
        #pragma unroll
        for (int off = 16; off; off >>= 1)
            v += __shfl_down_sync(0xffffffffu, v, off);
        if (lane == 0) rec[node] = v + b2s;
    }
}

// ----------------------------------------------------------------------------
extern "C" void kernel_launch(void* const* d_in, const int* in_sizes, int n_in,
                              void* d_out, int out_size)
{
    const float* h      = (const float*)d_in[0];
    const int*   src    = (const int*)  d_in[1];
    const int*   dst    = (const int*)  d_in[2];
    const int*   ety    = (const int*)  d_in[3];
    const float* norm   = (const float*)d_in[4];
    const float* bases0 = (const float*)d_in[5];
    const float* wcomp0 = (const float*)d_in[6];
    const float* bases1 = (const float*)d_in[7];
    const float* wcomp1 = (const float*)d_in[8];
    const float* bases2 = (const float*)d_in[9];
    const float* wcomp2 = (const float*)d_in[10];
    const float* dw1    = (const float*)d_in[11];
    const float* db1    = (const float*)d_in[12];
    const float* dw2    = (const float*)d_in[13];
    const float* db2    = (const float*)d_in[14];

    float* out  = (float*)d_out;
    float* rec  = out;                 // [N]
    float* henc = out + NND;           // [N, D]

    float *h1, *h2;
    int *deg, *rowptr;
    ull *edata, *partial;
    uint *ahi, *alo, *bth, *btl;
    cudaGetSymbolAddress((void**)&h1, g_h1);
    cudaGetSymbolAddress((void**)&h2, g_h2);
    cudaGetSymbolAddress((void**)&deg, g_deg);
    cudaGetSymbolAddress((void**)&rowptr, g_rowptr);
    cudaGetSymbolAddress((void**)&edata, g_edata);
    cudaGetSymbolAddress((void**)&partial, g_partial);
    cudaGetSymbolAddress((void**)&ahi, g_Ahi);
    cudaGetSymbolAddress((void**)&alo, g_Alo);
    cudaGetSymbolAddress((void**)&bth, g_Bth);
    cudaGetSymbolAddress((void**)&btl, g_Btl);

    // ---- CSR by dst (once, reused 3x) ----
    cudaMemsetAsync(deg, 0, NND * sizeof(int));
    cudaMemsetAsync(partial, 0, NCH * sizeof(ull));
    hist_kernel<<<1024, 256>>>(dst);                        // launch 1
    scan_kernel<<<NCH, 256>>>();                            // launch 2
    csr_scatter_kernel<<<1024, 256>>>(src, dst, ety, norm); // launch 3

    // ---- 3 layers: p1 (gather+aggregate) then p2 (HMMA GEMM) ----
    p1_kernel<<<1184, 256>>>(h, wcomp0, rowptr, edata, ahi, alo); // launch 4
    bprep_kernel<<<(3 * 64 * 128 + 255) / 256, 256>>>(bases0, bases1, bases2);
    p2_kernel<<<NT2, 256>>>(ahi, alo, bth, btl, h1, 1);

    p1_kernel<<<1184, 256>>>(h1, wcomp1, rowptr, edata, ahi, alo);
    p2_kernel<<<NT2, 256>>>(ahi, alo, bth + 64 * 128, btl + 64 * 128, h2, 1);

    p1_kernel<<<1184, 256>>>(h2, wcomp2, rowptr, edata, ahi, alo);
    p2_kernel<<<NT2, 256>>>(ahi, alo, bth + 2 * 64 * 128, btl + 2 * 64 * 128, henc, 0);

    // ---- decoder ----
    decoder_kernel<<<2048, 256>>>(henc, dw1, db1, dw2, db2, rec);
}

// round 15
// speedup vs baseline: 2.2930x; 2.2930x over previous
#include <cuda_runtime.h>
#include <cuda_bf16.h>
#include <cstddef>
#include <cstdint>

#define NND 100000
#define NPAD 100096                  // padded to multiple of 128
#define EE  1600000
#define RR  8
#define BB  4
#define DD  64
#define NCH ((NND + 1023) / 1024)    // 98 scan chunks
#define NT2 (NPAD / 128)             // 782 p2 tiles

typedef unsigned long long ull;
typedef unsigned int uint;

// Scratch (no runtime allocation allowed) ------------------------------------
__device__ float g_h1[(size_t)NND * DD];
__device__ float g_h2[(size_t)NND * DD];
__device__ uint2 g_Ahl[(size_t)NPAD * 128];   // aggB (hi,lo) bf16 pairs, 102.5MB
__device__ uint4 g_Bf[3][16 * 8 * 32];        // B frags per layer (fragment order)
__device__ int   g_deg[NND];
__device__ int   g_rowptr[NND + 1];
__device__ int   g_cur[NND];
__device__ ull   g_partial[NCH];
__device__ ull   g_edata[EE];                 // (norm<<32)|(ety<<20)|src

// ---------------------------------------------------------------- f32x2 utils
__device__ __forceinline__ void fma2(ull& a, ull x, ull b) {
    asm("fma.rn.f32x2 %0, %1, %2, %0;" : "+l"(a) : "l"(x), "l"(b));
}
__device__ __forceinline__ ull mul2(ull x, ull y) {
    ull r; asm("mul.rn.f32x2 %0, %1, %2;" : "=l"(r) : "l"(x), "l"(y)); return r;
}
__device__ __forceinline__ ull dup2(float x) {
    ull r; asm("mov.b64 %0, {%1, %1};" : "=l"(r) : "f"(x)); return r;
}
__device__ __forceinline__ float2 unp2(ull v) {
    float2 r; asm("mov.b64 {%0, %1}, %2;" : "=f"(r.x), "=f"(r.y) : "l"(v));
    return r;
}

// pack (x -> low 16, y -> high 16) as bf16x2
#define CVTBF2(r, x, y) \
    asm("cvt.rn.bf16x2.f32 %0, %1, %2;" : "=r"(r) : "f"(y), "f"(x))

// split a packed fp32 pair into bf16 hi + bf16 lo(residual)
__device__ __forceinline__ void bf16split(ull a, uint& h, uint& l) {
    const float2 v = unp2(a);
    CVTBF2(h, v.x, v.y);
    const float fx = __uint_as_float(h << 16);
    const float fy = __uint_as_float(h & 0xFFFF0000u);
    CVTBF2(l, v.x - fx, v.y - fy);
}

// legacy HMMA: m16n8k16 bf16*bf16 + f32 (baseline PTX, no 'a' features)
#define MMA(c, a0, a1, a2, a3, b0, b1) \
    asm volatile("mma.sync.aligned.m16n8k16.row.col.f32.bf16.bf16.f32 " \
        "{%0,%1,%2,%3}, {%4,%5,%6,%7}, {%8,%9}, {%0,%1,%2,%3};" \
        : "+f"((c)[0]), "+f"((c)[1]), "+f"((c)[2]), "+f"((c)[3]) \
        : "r"(a0), "r"(a1), "r"(a2), "r"(a3), "r"(b0), "r"(b1))

// ----------------------------------------------------------------- CSR build
__global__ void __launch_bounds__(256) hist_kernel(const int* __restrict__ dst) {
    for (long long e = (long long)blockIdx.x * 256 + threadIdx.x; e < EE;
         e += (long long)gridDim.x * 256)
        atomicAdd(&g_deg[dst[e]], 1);
}

__global__ void __launch_bounds__(256) scan_kernel() {
    __shared__ int s[256];
    __shared__ int pre;
    const int b = blockIdx.x, t = threadIdx.x;

    int v[4];
    #pragma unroll
    for (int j = 0; j < 4; j++) {
        int i = b * 1024 + t * 4 + j;
        v[j] = (i < NND) ? g_deg[i] : 0;
    }
    const int tot = v[0] + v[1] + v[2] + v[3];
    s[t] = tot; __syncthreads();
    for (int off = 1; off < 256; off <<= 1) {
        int x = (t >= off) ? s[t - off] : 0;
        __syncthreads();
        s[t] += x;
        __syncthreads();
    }
    if (t == 255)
        atomicExch(&g_partial[b], (1ull << 32) | (uint)s[255]);

    __shared__ int predsum[128];
    if (t < 128) predsum[t] = 0;
    __syncthreads();
    if (t < b) {
        ull p;
        do { p = atomicAdd(&g_partial[t], 0ull); } while (!(p >> 32));
        predsum[t] = (int)(uint)p;
    }
    __syncthreads();
    if (t == 0) {
        int acc = 0;
        for (int i = 0; i < b; i++) acc += predsum[i];
        pre = acc;
    }
    __syncthreads();

    int run = pre + s[t] - tot;
    #pragma unroll
    for (int j = 0; j < 4; j++) {
        int i = b * 1024 + t * 4 + j;
        if (i < NND) { g_rowptr[i] = run; g_cur[i] = run; }
        run += v[j];
    }
    if (b == 0 && t == 0) g_rowptr[NND] = EE;
}

__global__ void __launch_bounds__(256) csr_scatter_kernel(
    const int* __restrict__ src, const int* __restrict__ dst,
    const int* __restrict__ ety, const float* __restrict__ norm)
{
    for (long long e = (long long)blockIdx.x * 256 + threadIdx.x; e < EE;
         e += (long long)gridDim.x * 256) {
        const int d = dst[e];
        const int pos = atomicAdd(&g_cur[d], 1);
        const ull v = ((ull)__float_as_uint(norm[e]) << 32)
                    | (uint)(src[e] | (ety[e] << 20));
        g_edata[pos] = v;
    }
}

// ----------------------------------------------------------------------------
// B prep in FRAGMENT ORDER: Bf[layer][(ks*8+nt)*32 + lane] = {bh0,bh1,bl0,bl1}
// lane=(g,tig): o = nt*8+g; kp0 = ks*8+tig; kp1 = kp0+4; k = 2*kp.
// One thread per (layer, ks, nt, lane): 3*16*8*32 = 12288 threads.
// ----------------------------------------------------------------------------
__global__ void __launch_bounds__(256) bprep_kernel(
    const float* __restrict__ b0, const float* __restrict__ b1,
    const float* __restrict__ b2)
{
    const int idx = blockIdx.x * 256 + threadIdx.x;
    if (idx >= 3 * 4096) return;
    const int layer = idx >> 12;
    const int rem = idx & 4095;
    const int ks = rem >> 8;
    const int nt = (rem >> 5) & 7;
    const int lane = rem & 31;
    const int g = lane >> 2, tig = lane & 3;
    const int o = nt * 8 + g;
    const float* bp = (layer == 0) ? b0 : (layer == 1) ? b1 : b2;

    uint hv[2], lv[2];
    #pragma unroll
    for (int q = 0; q < 2; q++) {
        const int kp = ks * 8 + tig + q * 4;
        const int k = 2 * kp;
        const int b = k >> 6, i = k & 63;
        const float v0 = bp[b * DD * DD + i * DD + o];
        const float v1 = bp[b * DD * DD + (i + 1) * DD + o];
        uint h; CVTBF2(h, v0, v1);
        const float f0 = __uint_as_float(h << 16);
        const float f1 = __uint_as_float(h & 0xFFFF0000u);
        uint l; CVTBF2(l, v0 - f0, v1 - f1);
        hv[q] = h; lv[q] = l;
    }
    g_Bf[layer][(ks * 8 + nt) * 32 + lane] = make_uint4(hv[0], hv[1], lv[0], lv[1]);
}

// ----------------------------------------------------------------------------
// Phase 1: aggB[row][b*64+2*lane..] = sum_{e->row} wcomp[ety,b]*norm * X[src]
// warp per row, 8 edges in flight; stores interleaved (hi,lo) uint2 per pair.
// ----------------------------------------------------------------------------
__global__ void __launch_bounds__(256) p1_kernel(
    const float* __restrict__ Xin, const float* __restrict__ wcomp,
    const int* __restrict__ rowptr, const ull* __restrict__ edata,
    uint2* __restrict__ Ahl)
{
    __shared__ ull wc2[RR * BB];
    const int tid = threadIdx.x;
    if (tid < RR * BB) wc2[tid] = dup2(wcomp[tid]);
    __syncthreads();

    const int lane = tid & 31;
    const int gw = blockIdx.x * 8 + (tid >> 5);
    const int W = gridDim.x * 8;

    for (int row = gw; row < NND; row += W) {
        const int beg = rowptr[row];
        const int end = rowptr[row + 1];

        ull a0 = 0, a1 = 0, a2 = 0, a3 = 0;
        for (int e = beg; e < end; e += 8) {
            ull ed[8];
            #pragma unroll
            for (int j = 0; j < 8; j++) {
                const int idx = (e + j < end) ? e + j : end - 1;
                ed[j] = __ldg(edata + idx);
            }
            ull xv[8];
            #pragma unroll
            for (int j = 0; j < 8; j++) {
                const int s = (uint)ed[j] & 0xFFFFF;
                xv[j] = *(const ull*)(Xin + (size_t)s * DD + 2 * lane);
            }
            #pragma unroll
            for (int j = 0; j < 8; j++) {
                float nm = __uint_as_float((uint)(ed[j] >> 32));
                if (e + j >= end) nm = 0.f;
                const int r = ((uint)ed[j] >> 20) & 7;
                const ull xnm = mul2(xv[j], dup2(nm));
                const ulonglong2 wA = *(const ulonglong2*)&wc2[r * 4 + 0];
                const ulonglong2 wB = *(const ulonglong2*)&wc2[r * 4 + 2];
                fma2(a0, wA.x, xnm);
                fma2(a1, wA.y, xnm);
                fma2(a2, wB.x, xnm);
                fma2(a3, wB.y, xnm);
            }
        }
        uint h, l;
        uint2* p = Ahl + (size_t)row * 128 + lane;
        bf16split(a0, h, l); p[0]  = make_uint2(h, l);
        bf16split(a1, h, l); p[32] = make_uint2(h, l);
        bf16split(a2, h, l); p[64] = make_uint2(h, l);
        bf16split(a3, h, l); p[96] = make_uint2(h, l);
    }
}

// ----------------------------------------------------------------------------
// Phase 2 (HMMA): Out[128-tile][64] = aggB @ B^T via 3-term bf16 split.
// 8 warps x (M16 x N64); A: 4 coalesced-ish LDG.64/kstep; B: 1 contiguous
// LDG.128 per (kstep, nt). fp32 accum; fused ReLU on store.
// ----------------------------------------------------------------------------
__global__ void __launch_bounds__(256) p2_kernel(
    const uint2* __restrict__ Ahl, const uint4* __restrict__ Bf,
    float* __restrict__ Out, int relu_out)
{
    const int tid = threadIdx.x;
    const int warp = tid >> 5, lane = tid & 31;
    const int g = lane >> 2, tig = lane & 3;
    const int m0 = blockIdx.x * 128 + warp * 16;

    float acc[8][4];
    #pragma unroll
    for (int n = 0; n < 8; n++) {
        acc[n][0] = 0.f; acc[n][1] = 0.f; acc[n][2] = 0.f; acc[n][3] = 0.f;
    }

    const uint2* a0p = Ahl + (size_t)(m0 + g) * 128 + tig;
    const uint2* a1p = Ahl + (size_t)(m0 + g + 8) * 128 + tig;
    const uint4* bf = Bf + lane;

    #pragma unroll 4
    for (int ks = 0; ks < 16; ks++) {
        const int ku = ks * 8;
        const uint2 A0 = __ldg(a0p + ku);
        const uint2 A1 = __ldg(a1p + ku);
        const uint2 A2 = __ldg(a0p + ku + 4);
        const uint2 A3 = __ldg(a1p + ku + 4);
        #pragma unroll
        for (int nt = 0; nt < 8; nt++) {
            const uint4 bv = __ldg(bf + (ks * 8 + nt) * 32);
            MMA(acc[nt], A0.x, A1.x, A2.x, A3.x, bv.x, bv.y);  // hi*hi
            MMA(acc[nt], A0.x, A1.x, A2.x, A3.x, bv.z, bv.w);  // hi*lo
            MMA(acc[nt], A0.y, A1.y, A2.y, A3.y, bv.x, bv.y);  // lo*hi
        }
    }

    const int r0 = m0 + g, r1 = m0 + g + 8;
    #pragma unroll
    for (int nt = 0; nt < 8; nt++) {
        float2 v0 = make_float2(acc[nt][0], acc[nt][1]);
        float2 v1 = make_float2(acc[nt][2], acc[nt][3]);
        if (relu_out) {
            v0.x = fmaxf(v0.x, 0.f); v0.y = fmaxf(v0.y, 0.f);
            v1.x = fmaxf(v1.x, 0.f); v1.y = fmaxf(v1.y, 0.f);
        }
        const int c = nt * 8 + 2 * tig;
        if (r0 < NND) *(float2*)(Out + (size_t)r0 * DD + c) = v0;
        if (r1 < NND) *(float2*)(Out + (size_t)r1 * DD + c) = v1;
    }
}

// ----------------------------------------------------------------------------
// Decoder: rec[n] = (relu(henc[n] @ W1 + b1)) @ W2 + b2.  One warp per node.
// ----------------------------------------------------------------------------
__global__ void __launch_bounds__(256) decoder_kernel(
    const float* __restrict__ henc, const float* __restrict__ w1,
    const float* __restrict__ b1, const float* __restrict__ w2,
    const float* __restrict__ b2, float* __restrict__ rec)
{
    __shared__ float w1s[DD * DD];
    __shared__ float w2s[DD], b1s[DD];
    __shared__ float b2s;
    const int tid = threadIdx.x;
    for (int i = tid; i < DD * DD; i += 256) w1s[i] = w1[i];
    if (tid < DD) { w2s[tid] = w2[tid]; b1s[tid] = b1[tid]; }
    if (tid == 0) b2s = b2[0];
    __syncthreads();

    const int lane = tid & 31;
    const int w = tid >> 5;
    for (int node = blockIdx.x * 8 + w; node < NND; node += gridDim.x * 8) {
        const float xa = henc[(size_t)node * DD + lane];
        const float xb = henc[(size_t)node * DD + 32 + lane];
        float s0 = b1s[lane], s1 = b1s[lane + 32];
        #pragma unroll
        for (int i = 0; i < 32; i++) {
            const float xi = __shfl_sync(0xffffffffu, xa, i);
            s0 += xi * w1s[i * DD + lane];
            s1 += xi * w1s[i * DD + lane + 32];
        }
        #pragma unroll
        for (int i = 0; i < 32; i++) {
            const float xi = __shfl_sync(0xffffffffu, xb, i);
            s0 += xi * w1s[(32 + i) * DD + lane];
            s1 += xi * w1s[(32 + i) * DD + lane + 32];
        }
        s0 = fmaxf(s0, 0.f); s1 = fmaxf(s1, 0.f);
        float v = s0 * w2s[lane] + s1 * w2s[lane + 32];
        #pragma unroll
        for (int off = 16; off; off >>= 1)
            v += __shfl_down_sync(0xffffffffu, v, off);
        if (lane == 0) rec[node] = v + b2s;
    }
}

// ----------------------------------------------------------------------------
extern "C" void kernel_launch(void* const* d_in, const int* in_sizes, int n_in,
                              void* d_out, int out_size)
{
    const float* h      = (const float*)d_in[0];
    const int*   src    = (const int*)  d_in[1];
    const int*   dst    = (const int*)  d_in[2];
    const int*   ety    = (const int*)  d_in[3];
    const float* norm   = (const float*)d_in[4];
    const float* bases0 = (const float*)d_in[5];
    const float* wcomp0 = (const float*)d_in[6];
    const float* bases1 = (const float*)d_in[7];
    const float* wcomp1 = (const float*)d_in[8];
    const float* bases2 = (const float*)d_in[9];
    const float* wcomp2 = (const float*)d_in[10];
    const float* dw1    = (const float*)d_in[11];
    const float* db1    = (const float*)d_in[12];
    const float* dw2    = (const float*)d_in[13];
    const float* db2    = (const float*)d_in[14];

    float* out  = (float*)d_out;
    float* rec  = out;                 // [N]
    float* henc = out + NND;           // [N, D]

    float *h1, *h2;
    int *deg, *rowptr;
    ull *edata, *partial;
    uint2* ahl;
    uint4* bf;
    cudaGetSymbolAddress((void**)&h1, g_h1);
    cudaGetSymbolAddress((void**)&h2, g_h2);
    cudaGetSymbolAddress((void**)&deg, g_deg);
    cudaGetSymbolAddress((void**)&rowptr, g_rowptr);
    cudaGetSymbolAddress((void**)&edata, g_edata);
    cudaGetSymbolAddress((void**)&partial, g_partial);
    cudaGetSymbolAddress((void**)&ahl, g_Ahl);
    cudaGetSymbolAddress((void**)&bf, g_Bf);

    // ---- CSR by dst (once, reused 3x) ----
    cudaMemsetAsync(deg, 0, NND * sizeof(int));
    cudaMemsetAsync(partial, 0, NCH * sizeof(ull));
    hist_kernel<<<1024, 256>>>(dst);                        // launch 1
    scan_kernel<<<NCH, 256>>>();                            // launch 2
    csr_scatter_kernel<<<1024, 256>>>(src, dst, ety, norm); // launch 3

    // ---- 3 layers: p1 (gather+aggregate) then p2 (HMMA GEMM) ----
    p1_kernel<<<1184, 256>>>(h, wcomp0, rowptr, edata, ahl);   // launch 4
    bprep_kernel<<<(3 * 4096 + 255) / 256, 256>>>(bases0, bases1, bases2);
    p2_kernel<<<NT2, 256>>>(ahl, bf, h1, 1);

    p1_kernel<<<1184, 256>>>(h1, wcomp1, rowptr, edata, ahl);
    p2_kernel<<<NT2, 256>>>(ahl, bf + 4096, h2, 1);

    p1_kernel<<<1184, 256>>>(h2, wcomp2, rowptr, edata, ahl);
    p2_kernel<<<NT2, 256>>>(ahl, bf + 2 * 4096, henc, 0);

    // ---- decoder ----
    decoder_kernel<<<2048, 256>>>(henc, dw1, db1, dw2, db2, rec);
}